// round 3
// baseline (speedup 1.0000x reference)
#include <cuda_runtime.h>
#include <cuda_fp16.h>
#include <stdint.h>

// Problem constants
#define NB      16384
#define INPUT   768
#define ACCSZ   1024
#define TM      128
#define TN      256
#define KC      64          // halves per K-chunk
#define NCHUNK  12          // 768/64
#define THREADS 512
#define M_TILES 256         // 32768/128  (stm rows then nstm rows)
#define N_TILES 4           // 1024/256
#define GRID_G  (M_TILES*N_TILES)

// SMEM layout (relative to 1024-aligned base)
#define A_STAGE   (TM*128)            // 16384 B (128 rows x 128B)
#define B_STAGE   (TN*128)            // 32768 B
#define A_REL     0
#define B_REL     (2*A_STAGE)         // 32768
#define UT_REL    (B_REL + 2*B_STAGE) // 98304
#define BIAS_REL  (UT_REL + TN*8*4)   // 106496
#define SEL_REL   (BIAS_REL + TN*4)   // 107520
#define SMEM_SIZE (SEL_REL + TM*4 + 1024)  // + alignment pad

// Pre-converted fp16 operands (written by prep kernel each launch)
__device__ __align__(16) __half g_a16[(size_t)2 * NB * INPUT];   // 48 MB
__device__ __align__(16) __half g_w16[(size_t)ACCSZ * INPUT];    // 1.5 MB

static __device__ __forceinline__ unsigned f2h2(float a, float b) {
    __half2 h = __floats2half2_rn(a, b);
    return *reinterpret_cast<unsigned*>(&h);
}

static __device__ __forceinline__ uint32_t smem_u32(const void* p) {
    uint32_t a;
    asm("{ .reg .u64 t; cvta.to.shared.u64 t, %1; cvt.u32.u64 %0, t; }" : "=r"(a) : "l"(p));
    return a;
}

static __device__ __forceinline__ uint32_t swz(uint32_t off) {
    return off ^ ((off >> 3) & 0x70);   // SW128 within 1KB block
}

static __device__ __forceinline__ void cp16(uint32_t dst, const void* src) {
    asm volatile("cp.async.cg.shared.global [%0], [%1], 16;" :: "r"(dst), "l"(src));
}

static __device__ __forceinline__ void ldsm4(uint32_t* r, uint32_t addr) {
    asm volatile("ldmatrix.sync.aligned.m8n8.x4.shared.b16 {%0,%1,%2,%3}, [%4];"
                 : "=r"(r[0]), "=r"(r[1]), "=r"(r[2]), "=r"(r[3]) : "r"(addr));
}

static __device__ __forceinline__ void mma16816(float* c, const uint32_t* a,
                                                const uint32_t* b) {
    asm volatile(
        "mma.sync.aligned.m16n8k16.row.col.f32.f16.f16.f32 "
        "{%0,%1,%2,%3}, {%4,%5,%6,%7}, {%8,%9}, {%0,%1,%2,%3};"
        : "+f"(c[0]), "+f"(c[1]), "+f"(c[2]), "+f"(c[3])
        : "r"(a[0]), "r"(a[1]), "r"(a[2]), "r"(a[3]), "r"(b[0]), "r"(b[1]));
}

// ---------------------------------------------------------------------------
// Prep: fp32 -> fp16 for embeddings (stm|nstm concatenated) and acc_w;
// init y[b] = out_b[sel[b]]
// ---------------------------------------------------------------------------
#define NA4 ((2 * NB * INPUT) / 4)   // 6291456
#define NW4 ((ACCSZ * INPUT) / 4)    // 196608

__global__ void nnue_prep(const float* __restrict__ stm,
                          const float* __restrict__ nstm,
                          const float* __restrict__ acc_w,
                          const int* __restrict__ selectors,
                          const float* __restrict__ out_b,
                          float* __restrict__ y) {
    int i = blockIdx.x * blockDim.x + threadIdx.x;
    if (i < NA4) {
        int e = i * 4;
        float4 v = (e < NB * INPUT)
                       ? *reinterpret_cast<const float4*>(stm + e)
                       : *reinterpret_cast<const float4*>(nstm + (e - NB * INPUT));
        uint2 h;
        h.x = f2h2(v.x, v.y);
        h.y = f2h2(v.z, v.w);
        *reinterpret_cast<uint2*>(g_a16 + e) = h;
    }
    if (i < NW4) {
        float4 v = *reinterpret_cast<const float4*>(acc_w + i * 4);
        uint2 h;
        h.x = f2h2(v.x, v.y);
        h.y = f2h2(v.z, v.w);
        *reinterpret_cast<uint2*>(g_w16 + i * 4) = h;
    }
    if (i < NB) y[i] = out_b[selectors[i]];
}

// ---------------------------------------------------------------------------
// Fused GEMM (mma.sync fp16) + bias + clip[0,6] + bucket-dot + atomicAdd
// Grid: 1024 CTAs (m_tile = bid>>2, n_tile = bid&3), 512 threads.
// Warp grid 4(m) x 4(n); warp tile 32x64.
// ---------------------------------------------------------------------------
__global__ void __launch_bounds__(THREADS, 1)
nnue_gemm(const int* __restrict__ selectors, const float* __restrict__ acc_b,
          const float* __restrict__ out_w, float* __restrict__ y) {
    extern __shared__ char smraw[];
    uint32_t raw = smem_u32(smraw);
    uint32_t sbase = (raw + 1023u) & ~1023u;
    char* sm = smraw + (sbase - raw);

    const int tid = threadIdx.x;
    const int lane = tid & 31;
    const int wid = tid >> 5;
    const int warp_m = wid & 3;   // 0..3 -> 32-row bands
    const int warp_n = wid >> 2;  // 0..3 -> 64-col bands

    const int n_tile = blockIdx.x & (N_TILES - 1);
    const int m_tile = blockIdx.x >> 2;
    const int n0 = n_tile * TN;
    const int src = (m_tile >= NB / TM) ? 1 : 0;

    float* s_ut = reinterpret_cast<float*>(sm + UT_REL);     // [256][8] col-major buckets
    float* s_bias = reinterpret_cast<float*>(sm + BIAS_REL); // [256]
    int* s_sel = reinterpret_cast<int*>(sm + SEL_REL);       // [128]

    // out_w transposed chunk: s_ut[cc*8+k] = out_w[k][src*1024 + n0 + cc]
#pragma unroll
    for (int i = tid; i < TN * 8; i += THREADS) {
        int cc = i >> 3, k = i & 7;
        s_ut[i] = out_w[k * 2048 + src * 1024 + n0 + cc];
    }
    if (tid < TN) s_bias[tid] = acc_b[n0 + tid];
    if (tid < TM) {
        int R = m_tile * TM + tid;
        int b = (R < NB) ? R : R - NB;
        s_sel[tid] = selectors[b];
    }

    const __half* Abase = g_a16 + (size_t)(m_tile * TM) * INPUT;
    const __half* Bbase = g_w16 + (size_t)n0 * INPUT;

    // ---- prefetch one K-chunk into stage (c&1) ----
    auto prefetch = [&](int c) {
        const int s = c & 1;
        const int k0 = c * KC;
        uint32_t dA = sbase + A_REL + s * A_STAGE;
#pragma unroll
        for (int j = 0; j < 2; ++j) {                 // 1024 segs of 16B
            int seg = tid + THREADS * j;
            int row = seg >> 3, c16 = seg & 7;
            cp16(dA + swz((uint32_t)(row * 128 + c16 * 16)),
                 Abase + (size_t)row * INPUT + k0 + c16 * 8);
        }
        uint32_t dB = sbase + B_REL + s * B_STAGE;
#pragma unroll
        for (int j = 0; j < 4; ++j) {                 // 2048 segs of 16B
            int seg = tid + THREADS * j;
            int row = seg >> 3, c16 = seg & 7;
            cp16(dB + swz((uint32_t)(row * 128 + c16 * 16)),
                 Bbase + (size_t)row * INPUT + k0 + c16 * 8);
        }
        asm volatile("cp.async.commit_group;" ::: "memory");
    };

    float acc[2][8][4] = {};

    prefetch(0);
#pragma unroll 1
    for (int c = 0; c < NCHUNK; ++c) {
        if (c + 1 < NCHUNK) {
            prefetch(c + 1);
            asm volatile("cp.async.wait_group 1;" ::: "memory");
        } else {
            asm volatile("cp.async.wait_group 0;" ::: "memory");
        }
        __syncthreads();

        const uint32_t sA = sbase + A_REL + (c & 1) * A_STAGE;
        const uint32_t sB = sbase + B_REL + (c & 1) * B_STAGE;

#pragma unroll
        for (int ks = 0; ks < 4; ++ks) {              // k16 steps
            uint32_t a[2][4], b[8][2];
#pragma unroll
            for (int mf = 0; mf < 2; ++mf) {
                int row = warp_m * 32 + mf * 16 + (lane & 15);
                int colh = ks * 16 + (lane >> 4) * 8;
                ldsm4(a[mf], sA + swz((uint32_t)(row * 128 + colh * 2)));
            }
#pragma unroll
            for (int np = 0; np < 4; ++np) {          // pairs of n8 frags
                int row = warp_n * 64 + np * 16 + (lane & 7) + ((lane >> 4) << 3);
                int colh = ks * 16 + ((lane >> 3) & 1) * 8;
                uint32_t r[4];
                ldsm4(r, sB + swz((uint32_t)(row * 128 + colh * 2)));
                b[np * 2 + 0][0] = r[0];
                b[np * 2 + 0][1] = r[1];
                b[np * 2 + 1][0] = r[2];
                b[np * 2 + 1][1] = r[3];
            }
#pragma unroll
            for (int mf = 0; mf < 2; ++mf)
#pragma unroll
                for (int nf = 0; nf < 8; ++nf)
                    mma16816(acc[mf][nf], a[mf], b[nf]);
        }
        __syncthreads();
    }

    // ---- fused epilogue: bias + clip + bucket dot + quad reduce + atomic ----
#pragma unroll
    for (int mf = 0; mf < 2; ++mf) {
#pragma unroll
        for (int h = 0; h < 2; ++h) {
            int r_loc = warp_m * 32 + mf * 16 + (lane >> 2) + h * 8;
            int sel = s_sel[r_loc];
            float p = 0.0f;
#pragma unroll
            for (int nf = 0; nf < 8; ++nf) {
                int col = warp_n * 64 + nf * 8 + (lane & 3) * 2;
                float v0 = acc[mf][nf][h * 2 + 0] + s_bias[col];
                v0 = fminf(fmaxf(v0, 0.0f), 6.0f);
                p += v0 * s_ut[col * 8 + sel];
                float v1 = acc[mf][nf][h * 2 + 1] + s_bias[col + 1];
                v1 = fminf(fmaxf(v1, 0.0f), 6.0f);
                p += v1 * s_ut[(col + 1) * 8 + sel];
            }
            p += __shfl_xor_sync(0xffffffffu, p, 1);
            p += __shfl_xor_sync(0xffffffffu, p, 2);
            if ((lane & 3) == 0) {
                int R = m_tile * TM + r_loc;
                int b = (R < NB) ? R : R - NB;
                atomicAdd(&y[b], p);
            }
        }
    }
}

// ---------------------------------------------------------------------------
extern "C" void kernel_launch(void* const* d_in, const int* in_sizes, int n_in,
                              void* d_out, int out_size) {
    const float* stm   = (const float*)d_in[0];
    const float* nstm  = (const float*)d_in[1];
    const int*   sel   = (const int*)d_in[2];
    const float* acc_w = (const float*)d_in[3];
    const float* acc_b = (const float*)d_in[4];
    const float* out_w = (const float*)d_in[5];
    const float* out_b = (const float*)d_in[6];
    float* y = (float*)d_out;

    nnue_prep<<<(NA4 + 255) / 256, 256>>>(stm, nstm, acc_w, sel, out_b, y);

    static int smem_set = 0;
    if (!smem_set) {
        cudaFuncSetAttribute(nnue_gemm, cudaFuncAttributeMaxDynamicSharedMemorySize,
                             SMEM_SIZE);
        smem_set = 1;
    }
    nnue_gemm<<<GRID_G, THREADS, SMEM_SIZE>>>(sel, acc_b, out_w, y);
}

// round 4
// speedup vs baseline: 1.0418x; 1.0418x over previous
#include <cuda_runtime.h>
#include <cuda_fp16.h>
#include <stdint.h>

// Problem constants
#define NB      16384
#define INPUT   768
#define ACCSZ   1024
#define TM      128
#define TN      256
#define KC      64          // halves per K-chunk
#define NCHUNK  12          // 768/64
#define THREADS 256
#define M_TILES 256         // 32768/128  (stm rows then nstm rows)
#define N_TILES 4           // 1024/256
#define GRID_G  (M_TILES*N_TILES)
#define NSTAGE  4

// SMEM layout (relative to 1024-aligned base)
#define A_STAGE   (TM*128)              // 16384 B (128 rows x 128B)
#define B_STAGE   (TN*128)              // 32768 B
#define STAGE_SZ  (A_STAGE + B_STAGE)   // 49152
#define A_REL     0
#define B_REL     A_STAGE
#define UT_REL    (NSTAGE*STAGE_SZ)     // 196608
#define BIAS_REL  (UT_REL + TN*8*4)     // 204800
#define SEL_REL   (BIAS_REL + TN*4)     // 205824
#define SMEM_SIZE (SEL_REL + TM*4 + 1024)

// Pre-converted fp16 operands (written by prep kernel each launch)
__device__ __align__(16) __half g_a16[(size_t)2 * NB * INPUT];   // 48 MB
__device__ __align__(16) __half g_w16[(size_t)ACCSZ * INPUT];    // 1.5 MB

static __device__ __forceinline__ unsigned f2h2(float a, float b) {
    __half2 h = __floats2half2_rn(a, b);
    return *reinterpret_cast<unsigned*>(&h);
}

static __device__ __forceinline__ uint32_t smem_u32(const void* p) {
    uint32_t a;
    asm("{ .reg .u64 t; cvta.to.shared.u64 t, %1; cvt.u32.u64 %0, t; }" : "=r"(a) : "l"(p));
    return a;
}

static __device__ __forceinline__ uint32_t swz(uint32_t off) {
    return off ^ ((off >> 3) & 0x70);   // SW128 within 1KB block
}

static __device__ __forceinline__ void cp16(uint32_t dst, const void* src) {
    asm volatile("cp.async.cg.shared.global [%0], [%1], 16;" :: "r"(dst), "l"(src));
}

static __device__ __forceinline__ void ldsm4(uint32_t* r, uint32_t addr) {
    asm volatile("ldmatrix.sync.aligned.m8n8.x4.shared.b16 {%0,%1,%2,%3}, [%4];"
                 : "=r"(r[0]), "=r"(r[1]), "=r"(r[2]), "=r"(r[3]) : "r"(addr));
}

static __device__ __forceinline__ void mma16816(float* c, const uint32_t* a,
                                                const uint32_t* b) {
    asm volatile(
        "mma.sync.aligned.m16n8k16.row.col.f32.f16.f16.f32 "
        "{%0,%1,%2,%3}, {%4,%5,%6,%7}, {%8,%9}, {%0,%1,%2,%3};"
        : "+f"(c[0]), "+f"(c[1]), "+f"(c[2]), "+f"(c[3])
        : "r"(a[0]), "r"(a[1]), "r"(a[2]), "r"(a[3]), "r"(b[0]), "r"(b[1]));
}

// ---------------------------------------------------------------------------
// Prep: fp32 -> fp16 for embeddings (stm|nstm concatenated) and acc_w;
// init y[b] = out_b[sel[b]]
// ---------------------------------------------------------------------------
#define NA4 ((2 * NB * INPUT) / 4)   // 6291456
#define NW4 ((ACCSZ * INPUT) / 4)    // 196608

__global__ void nnue_prep(const float* __restrict__ stm,
                          const float* __restrict__ nstm,
                          const float* __restrict__ acc_w,
                          const int* __restrict__ selectors,
                          const float* __restrict__ out_b,
                          float* __restrict__ y) {
    int i = blockIdx.x * blockDim.x + threadIdx.x;
    if (i < NA4) {
        int e = i * 4;
        float4 v = (e < NB * INPUT)
                       ? *reinterpret_cast<const float4*>(stm + e)
                       : *reinterpret_cast<const float4*>(nstm + (e - NB * INPUT));
        uint2 h;
        h.x = f2h2(v.x, v.y);
        h.y = f2h2(v.z, v.w);
        *reinterpret_cast<uint2*>(g_a16 + e) = h;
    }
    if (i < NW4) {
        float4 v = *reinterpret_cast<const float4*>(acc_w + i * 4);
        uint2 h;
        h.x = f2h2(v.x, v.y);
        h.y = f2h2(v.z, v.w);
        *reinterpret_cast<uint2*>(g_w16 + i * 4) = h;
    }
    if (i < NB) y[i] = out_b[selectors[i]];
}

// ---------------------------------------------------------------------------
// Fused GEMM (mma.sync fp16) + bias + clip[0,6] + bucket-dot + atomicAdd
// Grid: 1024 CTAs (m_tile = bid>>2, n_tile = bid&3), 256 threads.
// Warp grid 2(m) x 4(n); warp tile 64x64. 4-stage cp.async, distance 2.
// ---------------------------------------------------------------------------
__global__ void __launch_bounds__(THREADS, 1)
nnue_gemm(const int* __restrict__ selectors, const float* __restrict__ acc_b,
          const float* __restrict__ out_w, float* __restrict__ y) {
    extern __shared__ char smraw[];
    uint32_t raw = smem_u32(smraw);
    uint32_t sbase = (raw + 1023u) & ~1023u;
    char* sm = smraw + (sbase - raw);

    const int tid = threadIdx.x;
    const int lane = tid & 31;
    const int wid = tid >> 5;
    const int warp_m = wid >> 2;  // 0..1 -> 64-row bands
    const int warp_n = wid & 3;   // 0..3 -> 64-col bands

    const int n_tile = blockIdx.x & (N_TILES - 1);
    const int m_tile = blockIdx.x >> 2;
    const int n0 = n_tile * TN;
    const int src = (m_tile >= NB / TM) ? 1 : 0;

    float* s_ut = reinterpret_cast<float*>(sm + UT_REL);     // [256][8] col-major buckets
    float* s_bias = reinterpret_cast<float*>(sm + BIAS_REL); // [256]
    int* s_sel = reinterpret_cast<int*>(sm + SEL_REL);       // [128]

#pragma unroll
    for (int i = tid; i < TN * 8; i += THREADS) {
        int cc = i >> 3, k = i & 7;
        s_ut[i] = out_w[k * 2048 + src * 1024 + n0 + cc];
    }
    if (tid < TN) s_bias[tid] = acc_b[n0 + tid];
    if (tid < TM) {
        int R = m_tile * TM + tid;
        int b = (R < NB) ? R : R - NB;
        s_sel[tid] = selectors[b];
    }

    const __half* Abase = g_a16 + (size_t)(m_tile * TM) * INPUT;
    const __half* Bbase = g_w16 + (size_t)n0 * INPUT;

    // ---- prefetch one K-chunk into stage c % NSTAGE ----
    auto prefetch = [&](int c) {
        const int s = c & (NSTAGE - 1);
        const int k0 = c * KC;
        uint32_t dA = sbase + s * STAGE_SZ + A_REL;
#pragma unroll
        for (int j = 0; j < 4; ++j) {                 // 1024 segs of 16B
            int seg = tid + THREADS * j;
            int row = seg >> 3, c16 = seg & 7;
            cp16(dA + swz((uint32_t)(row * 128 + c16 * 16)),
                 Abase + (size_t)row * INPUT + k0 + c16 * 8);
        }
        uint32_t dB = sbase + s * STAGE_SZ + B_REL;
#pragma unroll
        for (int j = 0; j < 8; ++j) {                 // 2048 segs of 16B
            int seg = tid + THREADS * j;
            int row = seg >> 3, c16 = seg & 7;
            cp16(dB + swz((uint32_t)(row * 128 + c16 * 16)),
                 Bbase + (size_t)row * INPUT + k0 + c16 * 8);
        }
        asm volatile("cp.async.commit_group;" ::: "memory");
    };

    float acc[4][8][4] = {};

    prefetch(0);
    prefetch(1);
#pragma unroll 1
    for (int c = 0; c < NCHUNK; ++c) {
        if (c + 2 < NCHUNK) {
            prefetch(c + 2);
            asm volatile("cp.async.wait_group 2;" ::: "memory");
        } else if (c + 1 < NCHUNK) {
            asm volatile("cp.async.wait_group 1;" ::: "memory");
        } else {
            asm volatile("cp.async.wait_group 0;" ::: "memory");
        }
        __syncthreads();

        const uint32_t sA = sbase + (c & (NSTAGE - 1)) * STAGE_SZ + A_REL;
        const uint32_t sB = sbase + (c & (NSTAGE - 1)) * STAGE_SZ + B_REL;

#pragma unroll
        for (int ks = 0; ks < 4; ++ks) {              // k16 steps
            uint32_t a[4][4], b[8][2];
#pragma unroll
            for (int mf = 0; mf < 4; ++mf) {
                int row = warp_m * 64 + mf * 16 + (lane & 15);
                int colh = ks * 16 + (lane >> 4) * 8;
                ldsm4(a[mf], sA + swz((uint32_t)(row * 128 + colh * 2)));
            }
#pragma unroll
            for (int np = 0; np < 4; ++np) {          // pairs of n8 frags
                int row = warp_n * 64 + np * 16 + (lane & 7) + ((lane >> 4) << 3);
                int colh = ks * 16 + ((lane >> 3) & 1) * 8;
                uint32_t r[4];
                ldsm4(r, sB + swz((uint32_t)(row * 128 + colh * 2)));
                b[np * 2 + 0][0] = r[0];
                b[np * 2 + 0][1] = r[1];
                b[np * 2 + 1][0] = r[2];
                b[np * 2 + 1][1] = r[3];
            }
#pragma unroll
            for (int mf = 0; mf < 4; ++mf)
#pragma unroll
                for (int nf = 0; nf < 8; ++nf)
                    mma16816(acc[mf][nf], a[mf], b[nf]);
        }
    }

    // ---- fused epilogue: bias + clip + bucket dot + quad reduce + atomic ----
#pragma unroll
    for (int mf = 0; mf < 4; ++mf) {
#pragma unroll
        for (int h = 0; h < 2; ++h) {
            int r_loc = warp_m * 64 + mf * 16 + (lane >> 2) + h * 8;
            int sel = s_sel[r_loc];
            float p = 0.0f;
#pragma unroll
            for (int nf = 0; nf < 8; ++nf) {
                int col = warp_n * 64 + nf * 8 + (lane & 3) * 2;
                float v0 = acc[mf][nf][h * 2 + 0] + s_bias[col];
                v0 = fminf(fmaxf(v0, 0.0f), 6.0f);
                p += v0 * s_ut[col * 8 + sel];
                float v1 = acc[mf][nf][h * 2 + 1] + s_bias[col + 1];
                v1 = fminf(fmaxf(v1, 0.0f), 6.0f);
                p += v1 * s_ut[(col + 1) * 8 + sel];
            }
            p += __shfl_xor_sync(0xffffffffu, p, 1);
            p += __shfl_xor_sync(0xffffffffu, p, 2);
            if ((lane & 3) == 0) {
                int R = m_tile * TM + r_loc;
                int b = (R < NB) ? R : R - NB;
                atomicAdd(&y[b], p);
            }
        }
    }
}

// ---------------------------------------------------------------------------
extern "C" void kernel_launch(void* const* d_in, const int* in_sizes, int n_in,
                              void* d_out, int out_size) {
    const float* stm   = (const float*)d_in[0];
    const float* nstm  = (const float*)d_in[1];
    const int*   sel   = (const int*)d_in[2];
    const float* acc_w = (const float*)d_in[3];
    const float* acc_b = (const float*)d_in[4];
    const float* out_w = (const float*)d_in[5];
    const float* out_b = (const float*)d_in[6];
    float* y = (float*)d_out;

    nnue_prep<<<(NA4 + 255) / 256, 256>>>(stm, nstm, acc_w, sel, out_b, y);

    static int smem_set = 0;
    if (!smem_set) {
        cudaFuncSetAttribute(nnue_gemm, cudaFuncAttributeMaxDynamicSharedMemorySize,
                             SMEM_SIZE);
        smem_set = 1;
    }
    nnue_gemm<<<GRID_G, THREADS, SMEM_SIZE>>>(sel, acc_b, out_w, y);
}

// round 5
// speedup vs baseline: 1.0790x; 1.0357x over previous
#include <cuda_runtime.h>
#include <cuda_fp16.h>
#include <stdint.h>

// Problem constants
#define NB      16384
#define INPUT   768
#define ACCSZ   1024
#define TM      128
#define TN      128
#define KC      64          // halves per K-chunk
#define NCHUNK  12          // 768/64
#define THREADS 128
#define M_TILES 256         // 32768/128  (stm rows then nstm rows)
#define N_TILES 8           // 1024/128
#define GRID_G  (M_TILES*N_TILES)
#define NSTAGE  3

// SMEM layout (relative to 1024-aligned base)
#define A_STAGE   (TM*128)              // 16384 B (128 rows x 128B)
#define B_STAGE   (TN*128)              // 16384 B
#define STAGE_SZ  (A_STAGE + B_STAGE)   // 32768
#define A_REL     0
#define B_REL     A_STAGE
#define UT_REL    (NSTAGE*STAGE_SZ)     // 98304
#define BIAS_REL  (UT_REL + TN*8*4)     // 102400
#define SEL_REL   (BIAS_REL + TN*4)     // 102912
#define SMEM_SIZE (SEL_REL + TM*4 + 1024)  // 104448

// Pre-converted fp16 operands (written by prep kernel each launch)
__device__ __align__(16) __half g_a16[(size_t)2 * NB * INPUT];   // 48 MB
__device__ __align__(16) __half g_w16[(size_t)ACCSZ * INPUT];    // 1.5 MB

static __device__ __forceinline__ unsigned f2h2(float a, float b) {
    __half2 h = __floats2half2_rn(a, b);
    return *reinterpret_cast<unsigned*>(&h);
}

static __device__ __forceinline__ uint32_t smem_u32(const void* p) {
    uint32_t a;
    asm("{ .reg .u64 t; cvta.to.shared.u64 t, %1; cvt.u32.u64 %0, t; }" : "=r"(a) : "l"(p));
    return a;
}

static __device__ __forceinline__ uint32_t swz(uint32_t off) {
    return off ^ ((off >> 3) & 0x70);   // SW128 within 1KB block
}

static __device__ __forceinline__ void cp16(uint32_t dst, const void* src) {
    asm volatile("cp.async.cg.shared.global [%0], [%1], 16;" :: "r"(dst), "l"(src));
}

static __device__ __forceinline__ void ldsm4(uint32_t* r, uint32_t addr) {
    asm volatile("ldmatrix.sync.aligned.m8n8.x4.shared.b16 {%0,%1,%2,%3}, [%4];"
                 : "=r"(r[0]), "=r"(r[1]), "=r"(r[2]), "=r"(r[3]) : "r"(addr));
}

static __device__ __forceinline__ void mma16816(float* c, const uint32_t* a,
                                                const uint32_t* b) {
    asm volatile(
        "mma.sync.aligned.m16n8k16.row.col.f32.f16.f16.f32 "
        "{%0,%1,%2,%3}, {%4,%5,%6,%7}, {%8,%9}, {%0,%1,%2,%3};"
        : "+f"(c[0]), "+f"(c[1]), "+f"(c[2]), "+f"(c[3])
        : "r"(a[0]), "r"(a[1]), "r"(a[2]), "r"(a[3]), "r"(b[0]), "r"(b[1]));
}

// ---------------------------------------------------------------------------
// Prep: fp32 -> fp16 for embeddings (stm|nstm concatenated) and acc_w;
// init y[b] = out_b[sel[b]]
// ---------------------------------------------------------------------------
#define NA4 ((2 * NB * INPUT) / 4)   // 6291456
#define NW4 ((ACCSZ * INPUT) / 4)    // 196608

__global__ void nnue_prep(const float* __restrict__ stm,
                          const float* __restrict__ nstm,
                          const float* __restrict__ acc_w,
                          const int* __restrict__ selectors,
                          const float* __restrict__ out_b,
                          float* __restrict__ y) {
    int i = blockIdx.x * blockDim.x + threadIdx.x;
    if (i < NA4) {
        int e = i * 4;
        float4 v = (e < NB * INPUT)
                       ? *reinterpret_cast<const float4*>(stm + e)
                       : *reinterpret_cast<const float4*>(nstm + (e - NB * INPUT));
        uint2 h;
        h.x = f2h2(v.x, v.y);
        h.y = f2h2(v.z, v.w);
        *reinterpret_cast<uint2*>(g_a16 + e) = h;
    }
    if (i < NW4) {
        float4 v = *reinterpret_cast<const float4*>(acc_w + i * 4);
        uint2 h;
        h.x = f2h2(v.x, v.y);
        h.y = f2h2(v.z, v.w);
        *reinterpret_cast<uint2*>(g_w16 + i * 4) = h;
    }
    if (i < NB) y[i] = out_b[selectors[i]];
}

// ---------------------------------------------------------------------------
// Fused GEMM (mma.sync fp16) + bias + clip[0,6] + bucket-dot + atomicAdd
// Grid: 2048 CTAs (m_tile = bid>>3, n_tile = bid&7), 128 threads.
// Warp grid 2(m) x 2(n); warp tile 64x64. 3-stage cp.async, distance 2.
// 2 CTAs co-resident per SM for cross-CTA latency hiding.
// ---------------------------------------------------------------------------
__global__ void __launch_bounds__(THREADS, 2)
nnue_gemm(const int* __restrict__ selectors, const float* __restrict__ acc_b,
          const float* __restrict__ out_w, float* __restrict__ y) {
    extern __shared__ char smraw[];
    uint32_t raw = smem_u32(smraw);
    uint32_t sbase = (raw + 1023u) & ~1023u;
    char* sm = smraw + (sbase - raw);

    const int tid = threadIdx.x;
    const int lane = tid & 31;
    const int wid = tid >> 5;
    const int warp_m = wid >> 1;  // 0..1 -> 64-row bands
    const int warp_n = wid & 1;   // 0..1 -> 64-col bands

    const int n_tile = blockIdx.x & (N_TILES - 1);
    const int m_tile = blockIdx.x >> 3;
    const int n0 = n_tile * TN;
    const int src = (m_tile >= NB / TM) ? 1 : 0;

    float* s_ut = reinterpret_cast<float*>(sm + UT_REL);     // [128][8] col-major buckets
    float* s_bias = reinterpret_cast<float*>(sm + BIAS_REL); // [128]
    int* s_sel = reinterpret_cast<int*>(sm + SEL_REL);       // [128]

#pragma unroll
    for (int i = tid; i < TN * 8; i += THREADS) {
        int cc = i >> 3, k = i & 7;
        s_ut[i] = out_w[k * 2048 + src * 1024 + n0 + cc];
    }
    if (tid < TN) s_bias[tid] = acc_b[n0 + tid];
    {
        int R = m_tile * TM + tid;
        int b = (R < NB) ? R : R - NB;
        s_sel[tid] = selectors[b];
    }

    const __half* Abase = g_a16 + (size_t)(m_tile * TM) * INPUT;
    const __half* Bbase = g_w16 + (size_t)n0 * INPUT;

    // ---- prefetch one K-chunk into stage c % NSTAGE ----
    auto prefetch = [&](int c) {
        const int s = c % NSTAGE;
        const int k0 = c * KC;
        uint32_t dA = sbase + s * STAGE_SZ + A_REL;
#pragma unroll
        for (int j = 0; j < 8; ++j) {                 // 1024 segs of 16B
            int seg = tid + THREADS * j;
            int row = seg >> 3, c16 = seg & 7;
            cp16(dA + swz((uint32_t)(row * 128 + c16 * 16)),
                 Abase + (size_t)row * INPUT + k0 + c16 * 8);
        }
        uint32_t dB = sbase + s * STAGE_SZ + B_REL;
#pragma unroll
        for (int j = 0; j < 8; ++j) {                 // 1024 segs of 16B
            int seg = tid + THREADS * j;
            int row = seg >> 3, c16 = seg & 7;
            cp16(dB + swz((uint32_t)(row * 128 + c16 * 16)),
                 Bbase + (size_t)row * INPUT + k0 + c16 * 8);
        }
        asm volatile("cp.async.commit_group;" ::: "memory");
    };

    float acc[4][8][4] = {};

    prefetch(0);
    prefetch(1);
#pragma unroll 1
    for (int c = 0; c < NCHUNK; ++c) {
        if (c + 1 < NCHUNK) {
            asm volatile("cp.async.wait_group 1;" ::: "memory");
        } else {
            asm volatile("cp.async.wait_group 0;" ::: "memory");
        }
        __syncthreads();
        // Barrier above also protects stage (c+2)%3 == (c-1)%3 (its reads in
        // compute(c-1) completed before the barrier) from the write below.
        if (c + 2 < NCHUNK) prefetch(c + 2);

        const uint32_t sA = sbase + (c % NSTAGE) * STAGE_SZ + A_REL;
        const uint32_t sB = sbase + (c % NSTAGE) * STAGE_SZ + B_REL;

#pragma unroll
        for (int ks = 0; ks < 4; ++ks) {              // k16 steps
            uint32_t a[4][4], b[8][2];
#pragma unroll
            for (int mf = 0; mf < 4; ++mf) {
                int row = warp_m * 64 + mf * 16 + (lane & 15);
                int colh = ks * 16 + (lane >> 4) * 8;
                ldsm4(a[mf], sA + swz((uint32_t)(row * 128 + colh * 2)));
            }
#pragma unroll
            for (int np = 0; np < 4; ++np) {          // pairs of n8 frags
                int row = warp_n * 64 + np * 16 + (lane & 7) + ((lane >> 4) << 3);
                int colh = ks * 16 + ((lane >> 3) & 1) * 8;
                uint32_t r[4];
                ldsm4(r, sB + swz((uint32_t)(row * 128 + colh * 2)));
                b[np * 2 + 0][0] = r[0];
                b[np * 2 + 0][1] = r[1];
                b[np * 2 + 1][0] = r[2];
                b[np * 2 + 1][1] = r[3];
            }
#pragma unroll
            for (int mf = 0; mf < 4; ++mf)
#pragma unroll
                for (int nf = 0; nf < 8; ++nf)
                    mma16816(acc[mf][nf], a[mf], b[nf]);
        }
    }

    // ---- fused epilogue: bias + clip + bucket dot + quad reduce + atomic ----
#pragma unroll
    for (int mf = 0; mf < 4; ++mf) {
#pragma unroll
        for (int h = 0; h < 2; ++h) {
            int r_loc = warp_m * 64 + mf * 16 + (lane >> 2) + h * 8;
            int sel = s_sel[r_loc];
            float p = 0.0f;
#pragma unroll
            for (int nf = 0; nf < 8; ++nf) {
                int col = warp_n * 64 + nf * 8 + (lane & 3) * 2;
                float v0 = acc[mf][nf][h * 2 + 0] + s_bias[col];
                v0 = fminf(fmaxf(v0, 0.0f), 6.0f);
                p += v0 * s_ut[col * 8 + sel];
                float v1 = acc[mf][nf][h * 2 + 1] + s_bias[col + 1];
                v1 = fminf(fmaxf(v1, 0.0f), 6.0f);
                p += v1 * s_ut[(col + 1) * 8 + sel];
            }
            p += __shfl_xor_sync(0xffffffffu, p, 1);
            p += __shfl_xor_sync(0xffffffffu, p, 2);
            if ((lane & 3) == 0) {
                int R = m_tile * TM + r_loc;
                int b = (R < NB) ? R : R - NB;
                atomicAdd(&y[b], p);
            }
        }
    }
}

// ---------------------------------------------------------------------------
extern "C" void kernel_launch(void* const* d_in, const int* in_sizes, int n_in,
                              void* d_out, int out_size) {
    const float* stm   = (const float*)d_in[0];
    const float* nstm  = (const float*)d_in[1];
    const int*   sel   = (const int*)d_in[2];
    const float* acc_w = (const float*)d_in[3];
    const float* acc_b = (const float*)d_in[4];
    const float* out_w = (const float*)d_in[5];
    const float* out_b = (const float*)d_in[6];
    float* y = (float*)d_out;

    nnue_prep<<<(NA4 + 255) / 256, 256>>>(stm, nstm, acc_w, sel, out_b, y);

    static int smem_set = 0;
    if (!smem_set) {
        cudaFuncSetAttribute(nnue_gemm, cudaFuncAttributeMaxDynamicSharedMemorySize,
                             SMEM_SIZE);
        smem_set = 1;
    }
    nnue_gemm<<<GRID_G, THREADS, SMEM_SIZE>>>(sel, acc_b, out_w, y);
}

// round 6
// speedup vs baseline: 1.0953x; 1.0151x over previous
#include <cuda_runtime.h>
#include <cuda_fp16.h>
#include <stdint.h>

// Problem constants
#define NB      16384
#define INPUT   768
#define ACCSZ   1024
#define TM      128
#define TN      128
#define KC      64          // halves per K-chunk
#define NCHUNK  12          // 768/64
#define THREADS 256
#define M_TILES 256         // 32768/128  (stm rows then nstm rows)
#define N_TILES 8           // 1024/128
#define GRID_G  (M_TILES*N_TILES)
#define NSTAGE  3

// SMEM layout (relative to 1024-aligned base)
#define A_STAGE   (TM*128)              // 16384 B (128 rows x 128B)
#define B_STAGE   (TN*128)              // 16384 B
#define STAGE_SZ  (A_STAGE + B_STAGE)   // 32768
#define A_REL     0
#define B_REL     A_STAGE
#define UT_REL    (NSTAGE*STAGE_SZ)     // 98304
#define BIAS_REL  (UT_REL + TN*8*4)     // 102400
#define SEL_REL   (BIAS_REL + TN*4)     // 102912
#define SMEM_SIZE (SEL_REL + TM*4 + 1024)  // 104448

// Pre-converted fp16 operands (written by prep kernel each launch)
__device__ __align__(16) __half g_a16[(size_t)2 * NB * INPUT];   // 48 MB
__device__ __align__(16) __half g_w16[(size_t)ACCSZ * INPUT];    // 1.5 MB

static __device__ __forceinline__ unsigned f2h2(float a, float b) {
    __half2 h = __floats2half2_rn(a, b);
    return *reinterpret_cast<unsigned*>(&h);
}

static __device__ __forceinline__ uint32_t smem_u32(const void* p) {
    uint32_t a;
    asm("{ .reg .u64 t; cvta.to.shared.u64 t, %1; cvt.u32.u64 %0, t; }" : "=r"(a) : "l"(p));
    return a;
}

static __device__ __forceinline__ uint32_t swz(uint32_t off) {
    return off ^ ((off >> 3) & 0x70);   // SW128 within 1KB block
}

static __device__ __forceinline__ void cp16(uint32_t dst, const void* src) {
    asm volatile("cp.async.cg.shared.global [%0], [%1], 16;" :: "r"(dst), "l"(src));
}

static __device__ __forceinline__ void ldsm4(uint32_t* r, uint32_t addr) {
    asm volatile("ldmatrix.sync.aligned.m8n8.x4.shared.b16 {%0,%1,%2,%3}, [%4];"
                 : "=r"(r[0]), "=r"(r[1]), "=r"(r[2]), "=r"(r[3]) : "r"(addr));
}

static __device__ __forceinline__ void mma16816(float* c, const uint32_t* a,
                                                const uint32_t* b) {
    asm volatile(
        "mma.sync.aligned.m16n8k16.row.col.f32.f16.f16.f32 "
        "{%0,%1,%2,%3}, {%4,%5,%6,%7}, {%8,%9}, {%0,%1,%2,%3};"
        : "+f"(c[0]), "+f"(c[1]), "+f"(c[2]), "+f"(c[3])
        : "r"(a[0]), "r"(a[1]), "r"(a[2]), "r"(a[3]), "r"(b[0]), "r"(b[1]));
}

// ---------------------------------------------------------------------------
// Prep: fp32 -> fp16 for embeddings (stm|nstm concatenated) and acc_w;
// init y[b] = out_b[sel[b]]
// ---------------------------------------------------------------------------
#define NA4 ((2 * NB * INPUT) / 4)   // 6291456
#define NW4 ((ACCSZ * INPUT) / 4)    // 196608

__global__ void nnue_prep(const float* __restrict__ stm,
                          const float* __restrict__ nstm,
                          const float* __restrict__ acc_w,
                          const int* __restrict__ selectors,
                          const float* __restrict__ out_b,
                          float* __restrict__ y) {
    int i = blockIdx.x * blockDim.x + threadIdx.x;
    if (i < NA4) {
        int e = i * 4;
        float4 v = (e < NB * INPUT)
                       ? *reinterpret_cast<const float4*>(stm + e)
                       : *reinterpret_cast<const float4*>(nstm + (e - NB * INPUT));
        uint2 h;
        h.x = f2h2(v.x, v.y);
        h.y = f2h2(v.z, v.w);
        *reinterpret_cast<uint2*>(g_a16 + e) = h;
    }
    if (i < NW4) {
        float4 v = *reinterpret_cast<const float4*>(acc_w + i * 4);
        uint2 h;
        h.x = f2h2(v.x, v.y);
        h.y = f2h2(v.z, v.w);
        *reinterpret_cast<uint2*>(g_w16 + i * 4) = h;
    }
    if (i < NB) y[i] = out_b[selectors[i]];
}

// ---------------------------------------------------------------------------
// Fused GEMM (mma.sync fp16) + bias + clip[0,6] + bucket-dot + atomicAdd
// Grid: 2048 CTAs (m_tile = bid>>3, n_tile = bid&7), 256 threads.
// Warp grid 2(m) x 4(n); warp tile 64x32. 3-stage cp.async, distance 2.
// 2 CTAs co-resident per SM -> 16 warps/SM for latency hiding.
// ---------------------------------------------------------------------------
__global__ void __launch_bounds__(THREADS, 2)
nnue_gemm(const int* __restrict__ selectors, const float* __restrict__ acc_b,
          const float* __restrict__ out_w, float* __restrict__ y) {
    extern __shared__ char smraw[];
    uint32_t raw = smem_u32(smraw);
    uint32_t sbase = (raw + 1023u) & ~1023u;
    char* sm = smraw + (sbase - raw);

    const int tid = threadIdx.x;
    const int lane = tid & 31;
    const int wid = tid >> 5;
    const int warp_m = wid >> 2;  // 0..1 -> 64-row bands
    const int warp_n = wid & 3;   // 0..3 -> 32-col bands

    const int n_tile = blockIdx.x & (N_TILES - 1);
    const int m_tile = blockIdx.x >> 3;
    const int n0 = n_tile * TN;
    const int src = (m_tile >= NB / TM) ? 1 : 0;

    float* s_ut = reinterpret_cast<float*>(sm + UT_REL);     // [128][8] col-major buckets
    float* s_bias = reinterpret_cast<float*>(sm + BIAS_REL); // [128]
    int* s_sel = reinterpret_cast<int*>(sm + SEL_REL);       // [128]

#pragma unroll
    for (int i = tid; i < TN * 8; i += THREADS) {
        int cc = i >> 3, k = i & 7;
        s_ut[i] = out_w[k * 2048 + src * 1024 + n0 + cc];
    }
    if (tid < TN) s_bias[tid] = acc_b[n0 + tid];
    if (tid < TM) {
        int R = m_tile * TM + tid;
        int b = (R < NB) ? R : R - NB;
        s_sel[tid] = selectors[b];
    }

    const __half* Abase = g_a16 + (size_t)(m_tile * TM) * INPUT;
    const __half* Bbase = g_w16 + (size_t)n0 * INPUT;

    // ---- prefetch one K-chunk into stage c % NSTAGE ----
    auto prefetch = [&](int c) {
        const int s = c % NSTAGE;
        const int k0 = c * KC;
        uint32_t dA = sbase + s * STAGE_SZ + A_REL;
#pragma unroll
        for (int j = 0; j < 4; ++j) {                 // 1024 segs of 16B
            int seg = tid + THREADS * j;
            int row = seg >> 3, c16 = seg & 7;
            cp16(dA + swz((uint32_t)(row * 128 + c16 * 16)),
                 Abase + (size_t)row * INPUT + k0 + c16 * 8);
        }
        uint32_t dB = sbase + s * STAGE_SZ + B_REL;
#pragma unroll
        for (int j = 0; j < 4; ++j) {                 // 1024 segs of 16B
            int seg = tid + THREADS * j;
            int row = seg >> 3, c16 = seg & 7;
            cp16(dB + swz((uint32_t)(row * 128 + c16 * 16)),
                 Bbase + (size_t)row * INPUT + k0 + c16 * 8);
        }
        asm volatile("cp.async.commit_group;" ::: "memory");
    };

    float acc[4][4][4] = {};

    prefetch(0);
    prefetch(1);
#pragma unroll 1
    for (int c = 0; c < NCHUNK; ++c) {
        if (c + 1 < NCHUNK) {
            asm volatile("cp.async.wait_group 1;" ::: "memory");
        } else {
            asm volatile("cp.async.wait_group 0;" ::: "memory");
        }
        __syncthreads();
        // Barrier above also protects stage (c+2)%3 == (c-1)%3 (its reads in
        // compute(c-1) completed before the barrier) from the write below.
        if (c + 2 < NCHUNK) prefetch(c + 2);

        const uint32_t sA = sbase + (c % NSTAGE) * STAGE_SZ + A_REL;
        const uint32_t sB = sbase + (c % NSTAGE) * STAGE_SZ + B_REL;

#pragma unroll
        for (int ks = 0; ks < 4; ++ks) {              // k16 steps
            uint32_t a[4][4], b[4][2];
#pragma unroll
            for (int mf = 0; mf < 4; ++mf) {
                int row = warp_m * 64 + mf * 16 + (lane & 15);
                int colh = ks * 16 + (lane >> 4) * 8;
                ldsm4(a[mf], sA + swz((uint32_t)(row * 128 + colh * 2)));
            }
#pragma unroll
            for (int np = 0; np < 2; ++np) {          // pairs of n8 frags
                int row = warp_n * 32 + np * 16 + (lane & 7) + ((lane >> 4) << 3);
                int colh = ks * 16 + ((lane >> 3) & 1) * 8;
                uint32_t r[4];
                ldsm4(r, sB + swz((uint32_t)(row * 128 + colh * 2)));
                b[np * 2 + 0][0] = r[0];
                b[np * 2 + 0][1] = r[1];
                b[np * 2 + 1][0] = r[2];
                b[np * 2 + 1][1] = r[3];
            }
#pragma unroll
            for (int mf = 0; mf < 4; ++mf)
#pragma unroll
                for (int nf = 0; nf < 4; ++nf)
                    mma16816(acc[mf][nf], a[mf], b[nf]);
        }
    }

    // ---- fused epilogue: bias + clip + bucket dot + quad reduce + atomic ----
#pragma unroll
    for (int mf = 0; mf < 4; ++mf) {
#pragma unroll
        for (int h = 0; h < 2; ++h) {
            int r_loc = warp_m * 64 + mf * 16 + (lane >> 2) + h * 8;
            int sel = s_sel[r_loc];
            float p = 0.0f;
#pragma unroll
            for (int nf = 0; nf < 4; ++nf) {
                int col = warp_n * 32 + nf * 8 + (lane & 3) * 2;
                float v0 = acc[mf][nf][h * 2 + 0] + s_bias[col];
                v0 = fminf(fmaxf(v0, 0.0f), 6.0f);
                p += v0 * s_ut[col * 8 + sel];
                float v1 = acc[mf][nf][h * 2 + 1] + s_bias[col + 1];
                v1 = fminf(fmaxf(v1, 0.0f), 6.0f);
                p += v1 * s_ut[(col + 1) * 8 + sel];
            }
            p += __shfl_xor_sync(0xffffffffu, p, 1);
            p += __shfl_xor_sync(0xffffffffu, p, 2);
            if ((lane & 3) == 0) {
                int R = m_tile * TM + r_loc;
                int b = (R < NB) ? R : R - NB;
                atomicAdd(&y[b], p);
            }
        }
    }
}

// ---------------------------------------------------------------------------
extern "C" void kernel_launch(void* const* d_in, const int* in_sizes, int n_in,
                              void* d_out, int out_size) {
    const float* stm   = (const float*)d_in[0];
    const float* nstm  = (const float*)d_in[1];
    const int*   sel   = (const int*)d_in[2];
    const float* acc_w = (const float*)d_in[3];
    const float* acc_b = (const float*)d_in[4];
    const float* out_w = (const float*)d_in[5];
    const float* out_b = (const float*)d_in[6];
    float* y = (float*)d_out;

    nnue_prep<<<(NA4 + 255) / 256, 256>>>(stm, nstm, acc_w, sel, out_b, y);

    static int smem_set = 0;
    if (!smem_set) {
        cudaFuncSetAttribute(nnue_gemm, cudaFuncAttributeMaxDynamicSharedMemorySize,
                             SMEM_SIZE);
        smem_set = 1;
    }
    nnue_gemm<<<GRID_G, THREADS, SMEM_SIZE>>>(sel, acc_b, out_w, y);
}

// round 7
// speedup vs baseline: 1.0956x; 1.0002x over previous
#include <cuda_runtime.h>
#include <cuda_fp16.h>
#include <stdint.h>

// Problem constants
#define NB      16384
#define INPUT   768
#define ACCSZ   1024
#define TM      128
#define TN      128
#define KC      64          // halves per K-chunk
#define NCHUNK  12          // 768/64
#define THREADS 256
#define M_TILES 256         // 32768/128  (stm rows then nstm rows)
#define N_TILES 8           // 1024/128
#define GRID_G  (M_TILES*N_TILES)
#define NSTAGE  3

// SMEM layout (relative to 1024-aligned base)
#define A_STAGE   (TM*128)              // 16384 B (128 rows x 128B)
#define B_STAGE   (TN*128)              // 16384 B
#define STAGE_SZ  (A_STAGE + B_STAGE)   // 32768
#define A_REL     0
#define B_REL     A_STAGE
#define UT_REL    (NSTAGE*STAGE_SZ)     // 98304
#define BIAS_REL  (UT_REL + TN*8*4)     // 102400
#define SEL_REL   (BIAS_REL + TN*4)     // 102912
#define SMEM_SIZE (SEL_REL + TM*4 + 1024)  // 104448

// Pre-converted fp16 operands (written by prep kernel each launch)
__device__ __align__(16) __half g_a16[(size_t)2 * NB * INPUT];   // 48 MB
__device__ __align__(16) __half g_w16[(size_t)ACCSZ * INPUT];    // 1.5 MB

static __device__ __forceinline__ unsigned f2h2(float a, float b) {
    __half2 h = __floats2half2_rn(a, b);
    return *reinterpret_cast<unsigned*>(&h);
}

static __device__ __forceinline__ uint32_t smem_u32(const void* p) {
    uint32_t a;
    asm("{ .reg .u64 t; cvta.to.shared.u64 t, %1; cvt.u32.u64 %0, t; }" : "=r"(a) : "l"(p));
    return a;
}

static __device__ __forceinline__ uint32_t swz(uint32_t off) {
    return off ^ ((off >> 3) & 0x70);   // SW128 within 1KB block
}

static __device__ __forceinline__ void cp16(uint32_t dst, const void* src) {
    asm volatile("cp.async.cg.shared.global [%0], [%1], 16;" :: "r"(dst), "l"(src));
}

static __device__ __forceinline__ void ldsm4(uint32_t* r, uint32_t addr) {
    asm volatile("ldmatrix.sync.aligned.m8n8.x4.shared.b16 {%0,%1,%2,%3}, [%4];"
                 : "=r"(r[0]), "=r"(r[1]), "=r"(r[2]), "=r"(r[3]) : "r"(addr));
}

static __device__ __forceinline__ void mma16816(float* c, const uint32_t* a,
                                                const uint32_t* b) {
    asm volatile(
        "mma.sync.aligned.m16n8k16.row.col.f32.f16.f16.f32 "
        "{%0,%1,%2,%3}, {%4,%5,%6,%7}, {%8,%9}, {%0,%1,%2,%3};"
        : "+f"(c[0]), "+f"(c[1]), "+f"(c[2]), "+f"(c[3])
        : "r"(a[0]), "r"(a[1]), "r"(a[2]), "r"(a[3]), "r"(b[0]), "r"(b[1]));
}

// ---------------------------------------------------------------------------
// Prep: fp32 -> fp16 for embeddings (stm|nstm concatenated) and acc_w;
// init y[b] = out_b[sel[b]]
// ---------------------------------------------------------------------------
#define NA4 ((2 * NB * INPUT) / 4)   // 6291456
#define NW4 ((ACCSZ * INPUT) / 4)    // 196608

__global__ void nnue_prep(const float* __restrict__ stm,
                          const float* __restrict__ nstm,
                          const float* __restrict__ acc_w,
                          const int* __restrict__ selectors,
                          const float* __restrict__ out_b,
                          float* __restrict__ y) {
    int i = blockIdx.x * blockDim.x + threadIdx.x;
    if (i < NA4) {
        int e = i * 4;
        float4 v = (e < NB * INPUT)
                       ? *reinterpret_cast<const float4*>(stm + e)
                       : *reinterpret_cast<const float4*>(nstm + (e - NB * INPUT));
        uint2 h;
        h.x = f2h2(v.x, v.y);
        h.y = f2h2(v.z, v.w);
        *reinterpret_cast<uint2*>(g_a16 + e) = h;
    }
    if (i < NW4) {
        float4 v = *reinterpret_cast<const float4*>(acc_w + i * 4);
        uint2 h;
        h.x = f2h2(v.x, v.y);
        h.y = f2h2(v.z, v.w);
        *reinterpret_cast<uint2*>(g_w16 + i * 4) = h;
    }
    if (i < NB) y[i] = out_b[selectors[i]];
}

// ---------------------------------------------------------------------------
// Fused GEMM (mma.sync fp16) + bias + clip[0,6] + bucket-dot + atomicAdd
// Grid: 2048 CTAs (m_tile = bid>>3, n_tile = bid&7), 256 threads.
// Warp grid 2(m) x 4(n); warp tile 64x32. 3-stage cp.async, distance 2.
// 2 CTAs co-resident per SM -> 16 warps/SM for latency hiding.
// ---------------------------------------------------------------------------
__global__ void __launch_bounds__(THREADS, 2)
nnue_gemm(const int* __restrict__ selectors, const float* __restrict__ acc_b,
          const float* __restrict__ out_w, float* __restrict__ y) {
    extern __shared__ char smraw[];
    uint32_t raw = smem_u32(smraw);
    uint32_t sbase = (raw + 1023u) & ~1023u;
    char* sm = smraw + (sbase - raw);

    const int tid = threadIdx.x;
    const int lane = tid & 31;
    const int wid = tid >> 5;
    const int warp_m = wid >> 2;  // 0..1 -> 64-row bands
    const int warp_n = wid & 3;   // 0..3 -> 32-col bands

    const int n_tile = blockIdx.x & (N_TILES - 1);
    const int m_tile = blockIdx.x >> 3;
    const int n0 = n_tile * TN;
    const int src = (m_tile >= NB / TM) ? 1 : 0;

    float* s_ut = reinterpret_cast<float*>(sm + UT_REL);     // [128][8] col-major buckets
    float* s_bias = reinterpret_cast<float*>(sm + BIAS_REL); // [128]
    int* s_sel = reinterpret_cast<int*>(sm + SEL_REL);       // [128]

#pragma unroll
    for (int i = tid; i < TN * 8; i += THREADS) {
        int cc = i >> 3, k = i & 7;
        s_ut[i] = out_w[k * 2048 + src * 1024 + n0 + cc];
    }
    if (tid < TN) s_bias[tid] = acc_b[n0 + tid];
    if (tid < TM) {
        int R = m_tile * TM + tid;
        int b = (R < NB) ? R : R - NB;
        s_sel[tid] = selectors[b];
    }

    const __half* Abase = g_a16 + (size_t)(m_tile * TM) * INPUT;
    const __half* Bbase = g_w16 + (size_t)n0 * INPUT;

    // ---- prefetch one K-chunk into stage c % NSTAGE ----
    auto prefetch = [&](int c) {
        const int s = c % NSTAGE;
        const int k0 = c * KC;
        uint32_t dA = sbase + s * STAGE_SZ + A_REL;
#pragma unroll
        for (int j = 0; j < 4; ++j) {                 // 1024 segs of 16B
            int seg = tid + THREADS * j;
            int row = seg >> 3, c16 = seg & 7;
            cp16(dA + swz((uint32_t)(row * 128 + c16 * 16)),
                 Abase + (size_t)row * INPUT + k0 + c16 * 8);
        }
        uint32_t dB = sbase + s * STAGE_SZ + B_REL;
#pragma unroll
        for (int j = 0; j < 4; ++j) {                 // 1024 segs of 16B
            int seg = tid + THREADS * j;
            int row = seg >> 3, c16 = seg & 7;
            cp16(dB + swz((uint32_t)(row * 128 + c16 * 16)),
                 Bbase + (size_t)row * INPUT + k0 + c16 * 8);
        }
        asm volatile("cp.async.commit_group;" ::: "memory");
    };

    float acc[4][4][4] = {};

    prefetch(0);
    prefetch(1);
#pragma unroll 1
    for (int c = 0; c < NCHUNK; ++c) {
        if (c + 1 < NCHUNK) {
            asm volatile("cp.async.wait_group 1;" ::: "memory");
        } else {
            asm volatile("cp.async.wait_group 0;" ::: "memory");
        }
        __syncthreads();
        // Barrier above also protects stage (c+2)%3 == (c-1)%3 (its reads in
        // compute(c-1) completed before the barrier) from the write below.
        if (c + 2 < NCHUNK) prefetch(c + 2);

        const uint32_t sA = sbase + (c % NSTAGE) * STAGE_SZ + A_REL;
        const uint32_t sB = sbase + (c % NSTAGE) * STAGE_SZ + B_REL;

#pragma unroll
        for (int ks = 0; ks < 4; ++ks) {              // k16 steps
            uint32_t a[4][4], b[4][2];
#pragma unroll
            for (int mf = 0; mf < 4; ++mf) {
                int row = warp_m * 64 + mf * 16 + (lane & 15);
                int colh = ks * 16 + (lane >> 4) * 8;
                ldsm4(a[mf], sA + swz((uint32_t)(row * 128 + colh * 2)));
            }
#pragma unroll
            for (int np = 0; np < 2; ++np) {          // pairs of n8 frags
                int row = warp_n * 32 + np * 16 + (lane & 7) + ((lane >> 4) << 3);
                int colh = ks * 16 + ((lane >> 3) & 1) * 8;
                uint32_t r[4];
                ldsm4(r, sB + swz((uint32_t)(row * 128 + colh * 2)));
                b[np * 2 + 0][0] = r[0];
                b[np * 2 + 0][1] = r[1];
                b[np * 2 + 1][0] = r[2];
                b[np * 2 + 1][1] = r[3];
            }
#pragma unroll
            for (int mf = 0; mf < 4; ++mf)
#pragma unroll
                for (int nf = 0; nf < 4; ++nf)
                    mma16816(acc[mf][nf], a[mf], b[nf]);
        }
    }

    // ---- fused epilogue: bias + clip + bucket dot + quad reduce + atomic ----
#pragma unroll
    for (int mf = 0; mf < 4; ++mf) {
#pragma unroll
        for (int h = 0; h < 2; ++h) {
            int r_loc = warp_m * 64 + mf * 16 + (lane >> 2) + h * 8;
            int sel = s_sel[r_loc];
            float p = 0.0f;
#pragma unroll
            for (int nf = 0; nf < 4; ++nf) {
                int col = warp_n * 32 + nf * 8 + (lane & 3) * 2;
                float v0 = acc[mf][nf][h * 2 + 0] + s_bias[col];
                v0 = fminf(fmaxf(v0, 0.0f), 6.0f);
                p += v0 * s_ut[col * 8 + sel];
                float v1 = acc[mf][nf][h * 2 + 1] + s_bias[col + 1];
                v1 = fminf(fmaxf(v1, 0.0f), 6.0f);
                p += v1 * s_ut[(col + 1) * 8 + sel];
            }
            p += __shfl_xor_sync(0xffffffffu, p, 1);
            p += __shfl_xor_sync(0xffffffffu, p, 2);
            if ((lane & 3) == 0) {
                int R = m_tile * TM + r_loc;
                int b = (R < NB) ? R : R - NB;
                atomicAdd(&y[b], p);
            }
        }
    }
}

// ---------------------------------------------------------------------------
extern "C" void kernel_launch(void* const* d_in, const int* in_sizes, int n_in,
                              void* d_out, int out_size) {
    const float* stm   = (const float*)d_in[0];
    const float* nstm  = (const float*)d_in[1];
    const int*   sel   = (const int*)d_in[2];
    const float* acc_w = (const float*)d_in[3];
    const float* acc_b = (const float*)d_in[4];
    const float* out_w = (const float*)d_in[5];
    const float* out_b = (const float*)d_in[6];
    float* y = (float*)d_out;

    nnue_prep<<<(NA4 + 255) / 256, 256>>>(stm, nstm, acc_w, sel, out_b, y);

    static int smem_set = 0;
    if (!smem_set) {
        cudaFuncSetAttribute(nnue_gemm, cudaFuncAttributeMaxDynamicSharedMemorySize,
                             SMEM_SIZE);
        smem_set = 1;
    }
    nnue_gemm<<<GRID_G, THREADS, SMEM_SIZE>>>(sel, acc_b, out_w, y);
}